// round 1
// baseline (speedup 1.0000x reference)
#include <cuda_runtime.h>
#include <cuda_bf16.h>

// Problem constants: x[B,64,64] fp32, W[64,64,64] fp32, bias[64,64] fp32
// out[b,p,o] = relu(sum_k x[b,p,k]*W[p,k,o] + bias[p,o])

#define PP 64
#define KK 64
#define OO 64
#define BLOCK_B 128
#define XS_STRIDE 65   // 65 = 1 mod 32 -> conflict-free column reads

#define FMA2(d, a, b) \
    asm("fma.rn.f32x2 %0, %1, %2, %0;" : "+l"(d) : "l"(a), "l"(b))

__device__ __forceinline__ unsigned long long bcast2(float v) {
    unsigned long long r;
    asm("mov.b64 %0, {%1, %1};" : "=l"(r) : "f"(v));
    return r;
}

__device__ __forceinline__ void unpack2(unsigned long long v, float& lo, float& hi) {
    asm("mov.b64 {%0, %1}, %2;" : "=f"(lo), "=f"(hi) : "l"(v));
}

extern "C" __global__ void __launch_bounds__(128, 4)
parts_layer_kernel(const float* __restrict__ x,
                   const float* __restrict__ W,
                   const float* __restrict__ bias,
                   float* __restrict__ out)
{
    extern __shared__ float smem[];
    float* Xs = smem;                       // [BLOCK_B][XS_STRIDE]
    float* Ws = smem + BLOCK_B * XS_STRIDE; // [KK][OO] stride 64

    const int t  = threadIdx.x;
    const int p  = blockIdx.y;
    const int b0 = blockIdx.x * BLOCK_B;

    // ---- Load W[p]: 64x64 floats = 1024 float4, 128 threads x 8 ----
    const float* Wp = W + p * (KK * OO);
    #pragma unroll
    for (int i = 0; i < 8; i++) {
        int idx4 = i * 128 + t;
        ((float4*)Ws)[idx4] = ((const float4*)Wp)[idx4];
    }

    // ---- Load X tile: 128 rows x 64 = 2048 float4, scalar STS into padded rows ----
    #pragma unroll
    for (int i = 0; i < 16; i++) {
        int idx4 = i * 128 + t;
        int row  = idx4 >> 4;          // 16 float4 per row
        int c4   = idx4 & 15;
        float4 v = *(const float4*)(x + ((b0 + row) * PP + p) * KK + c4 * 4);
        float* dst = Xs + row * XS_STRIDE + c4 * 4;
        dst[0] = v.x; dst[1] = v.y; dst[2] = v.z; dst[3] = v.w;
    }
    __syncthreads();

    const int tx = t & 7;        // 8 col-groups
    const int ty = t >> 3;       // 16 row-groups
    const int r0 = ty * 8;       // 8 rows per thread
    const int c0 = tx * 8;       // 8 cols per thread (4 f32x2 pairs)

    unsigned long long acc[8][4];
    #pragma unroll
    for (int i = 0; i < 8; i++)
        #pragma unroll
        for (int j = 0; j < 4; j++)
            acc[i][j] = 0ULL;

    #pragma unroll 4
    for (int k = 0; k < KK; k++) {
        const float* wrow = Ws + k * OO + c0;
        unsigned long long w0 = *(const unsigned long long*)(wrow + 0);
        unsigned long long w1 = *(const unsigned long long*)(wrow + 2);
        unsigned long long w2 = *(const unsigned long long*)(wrow + 4);
        unsigned long long w3 = *(const unsigned long long*)(wrow + 6);
        #pragma unroll
        for (int i = 0; i < 8; i++) {
            unsigned long long xp = bcast2(Xs[(r0 + i) * XS_STRIDE + k]);
            FMA2(acc[i][0], xp, w0);
            FMA2(acc[i][1], xp, w1);
            FMA2(acc[i][2], xp, w2);
            FMA2(acc[i][3], xp, w3);
        }
    }

    // ---- Epilogue: bias + relu, coalesced float4 stores ----
    float bv[8];
    #pragma unroll
    for (int j = 0; j < 8; j++)
        bv[j] = bias[p * OO + c0 + j];

    #pragma unroll
    for (int i = 0; i < 8; i++) {
        float o[8];
        #pragma unroll
        for (int j = 0; j < 4; j++)
            unpack2(acc[i][j], o[2 * j], o[2 * j + 1]);
        #pragma unroll
        for (int j = 0; j < 8; j++)
            o[j] = fmaxf(o[j] + bv[j], 0.0f);

        float* dst = out + ((b0 + r0 + i) * PP + p) * OO + c0;
        *(float4*)(dst + 0) = make_float4(o[0], o[1], o[2], o[3]);
        *(float4*)(dst + 4) = make_float4(o[4], o[5], o[6], o[7]);
    }
}

extern "C" void kernel_launch(void* const* d_in, const int* in_sizes, int n_in,
                              void* d_out, int out_size)
{
    const float* x    = (const float*)d_in[0];
    const float* W    = (const float*)d_in[1];
    const float* bias = (const float*)d_in[2];
    float* out = (float*)d_out;

    const int B = in_sizes[0] / (PP * KK);   // 16384

    const int smem_bytes = (BLOCK_B * XS_STRIDE + KK * OO) * (int)sizeof(float); // 49664
    cudaFuncSetAttribute(parts_layer_kernel,
                         cudaFuncAttributeMaxDynamicSharedMemorySize, smem_bytes);

    dim3 grid(B / BLOCK_B, PP);
    parts_layer_kernel<<<grid, 128, smem_bytes>>>(x, W, bias, out);
}

// round 3
// speedup vs baseline: 1.4590x; 1.4590x over previous
#include <cuda_runtime.h>
#include <cuda_bf16.h>
#include <cstdint>

// out[b,p,o] = relu(sum_k x[b,p,k] * W[p,k,o] + bias[p,o])
// B=16384, P=K=O=64 fp32.
// CTA = 128 b-rows x one part p. Split-bf16 (hi+lo) x and W, 3 HMMA terms
// (hi*hi + hi*lo + lo*hi) with fp32 accumulators via mma.sync.m16n8k16.

#define PP 64
#define KK 64
#define OO 64
#define BLOCK_B 128
#define THREADS 128

#define ASTRIDE 72                    // bf16 elems per row: 144B, conflict-free LDSM
#define SA_BYTES (BLOCK_B * ASTRIDE * 2)   // 18432
#define SW_BYTES (KK * ASTRIDE * 2)        // 9216
#define SM_AHI 0
#define SM_ALO (SM_AHI + SA_BYTES)
#define SM_WHI (SM_ALO + SA_BYTES)
#define SM_WLO (SM_WHI + SW_BYTES)
#define SM_TOTAL (SM_WLO + SW_BYTES)       // 55296

__device__ __forceinline__ uint32_t smem_u32(const void* p) {
    uint32_t a;
    asm("{ .reg .u64 t; cvta.to.shared.u64 t, %1; cvt.u32.u64 %0, t; }" : "=r"(a) : "l"(p));
    return a;
}

// pack word: lo16 = bf16(a), hi16 = bf16(b)
__device__ __forceinline__ uint32_t pack_bf16(float a, float b) {
    uint32_t r;
    asm("cvt.rn.bf16x2.f32 %0, %1, %2;" : "=r"(r) : "f"(b), "f"(a));
    return r;
}
__device__ __forceinline__ float bf_lo(uint32_t h) { return __uint_as_float(h << 16); }
__device__ __forceinline__ float bf_hi(uint32_t h) { return __uint_as_float(h & 0xFFFF0000u); }

#define LDSM_X4(r0, r1, r2, r3, addr) \
    asm volatile("ldmatrix.sync.aligned.m8n8.x4.shared.b16 {%0,%1,%2,%3}, [%4];" \
                 : "=r"(r0), "=r"(r1), "=r"(r2), "=r"(r3) : "r"(addr))

#define LDSM_X4_T(r0, r1, r2, r3, addr) \
    asm volatile("ldmatrix.sync.aligned.m8n8.x4.trans.shared.b16 {%0,%1,%2,%3}, [%4];" \
                 : "=r"(r0), "=r"(r1), "=r"(r2), "=r"(r3) : "r"(addr))

#define MMA_BF16(d, a, b) \
    asm volatile("mma.sync.aligned.m16n8k16.row.col.f32.bf16.bf16.f32 " \
                 "{%0,%1,%2,%3}, {%4,%5,%6,%7}, {%8,%9}, {%0,%1,%2,%3};" \
                 : "+f"((d)[0]), "+f"((d)[1]), "+f"((d)[2]), "+f"((d)[3]) \
                 : "r"((a)[0]), "r"((a)[1]), "r"((a)[2]), "r"((a)[3]), \
                   "r"((b)[0]), "r"((b)[1]))

extern "C" __global__ void __launch_bounds__(THREADS, 4)
parts_hmma_kernel(const float* __restrict__ x,
                  const float* __restrict__ W,
                  const float* __restrict__ bias,
                  float* __restrict__ out)
{
    extern __shared__ char smem[];
    const uint32_t sb = smem_u32(smem);
    const int t    = threadIdx.x;
    const int wid  = t >> 5;
    const int lane = t & 31;
    const int p    = blockIdx.y;
    const int b0   = blockIdx.x * BLOCK_B;

    // ---- X tile: 128x64 fp32 -> bf16 hi/lo, smem stride 72 ----
    #pragma unroll
    for (int i = 0; i < 16; i++) {
        int idx4 = i * 128 + t;
        int row  = idx4 >> 4;            // 16 float4 per row
        int c4   = idx4 & 15;
        float4 v = *(const float4*)(x + (b0 + row) * (PP * KK) + p * KK + c4 * 4);
        uint32_t h0 = pack_bf16(v.x, v.y);
        uint32_t h1 = pack_bf16(v.z, v.w);
        uint32_t l0 = pack_bf16(v.x - bf_lo(h0), v.y - bf_hi(h0));
        uint32_t l1 = pack_bf16(v.z - bf_lo(h1), v.w - bf_hi(h1));
        uint32_t off = (uint32_t)(row * (ASTRIDE * 2) + c4 * 8);
        *(uint2*)(smem + SM_AHI + off) = make_uint2(h0, h1);
        *(uint2*)(smem + SM_ALO + off) = make_uint2(l0, l1);
    }

    // ---- W[p]: 64x64 fp32 -> bf16 hi/lo, row-major [k][o], stride 72 ----
    #pragma unroll
    for (int i = 0; i < 8; i++) {
        int idx4 = i * 128 + t;
        int k    = idx4 >> 4;
        int c4   = idx4 & 15;
        float4 v = *(const float4*)(W + p * (KK * OO) + k * OO + c4 * 4);
        uint32_t h0 = pack_bf16(v.x, v.y);
        uint32_t h1 = pack_bf16(v.z, v.w);
        uint32_t l0 = pack_bf16(v.x - bf_lo(h0), v.y - bf_hi(h0));
        uint32_t l1 = pack_bf16(v.z - bf_lo(h1), v.w - bf_hi(h1));
        uint32_t off = (uint32_t)(k * (ASTRIDE * 2) + c4 * 8);
        *(uint2*)(smem + SM_WHI + off) = make_uint2(h0, h1);
        *(uint2*)(smem + SM_WLO + off) = make_uint2(l0, l1);
    }
    __syncthreads();

    // ---- MMA mainloop: warp owns rows [wid*32, wid*32+32), all 64 cols ----
    const int w32   = wid * 32;
    const int lrow  = lane & 15;         // ldmatrix row within 16
    const int lcol8 = (lane >> 4) * 8;   // ldmatrix col-group

    float acc[2][8][4];
    #pragma unroll
    for (int mi = 0; mi < 2; mi++)
        #pragma unroll
        for (int ni = 0; ni < 8; ni++)
            #pragma unroll
            for (int r = 0; r < 4; r++)
                acc[mi][ni][r] = 0.0f;

    #pragma unroll
    for (int term = 0; term < 3; term++) {
        const uint32_t abase = sb + ((term == 2) ? SM_ALO : SM_AHI);
        const uint32_t bbase = sb + ((term == 1) ? SM_WLO : SM_WHI);

        #pragma unroll
        for (int ks = 0; ks < 4; ks++) {
            const int k0 = ks * 16;

            uint32_t a[2][4];
            #pragma unroll
            for (int mi = 0; mi < 2; mi++) {
                uint32_t addr = abase
                    + (uint32_t)((w32 + mi * 16 + lrow) * (ASTRIDE * 2)
                                 + (k0 + lcol8) * 2);
                LDSM_X4(a[mi][0], a[mi][1], a[mi][2], a[mi][3], addr);
            }

            uint32_t b[8][2];
            #pragma unroll
            for (int nj = 0; nj < 4; nj++) {
                uint32_t addr = bbase
                    + (uint32_t)((k0 + lrow) * (ASTRIDE * 2)
                                 + (nj * 16 + lcol8) * 2);
                LDSM_X4_T(b[nj * 2][0], b[nj * 2][1],
                          b[nj * 2 + 1][0], b[nj * 2 + 1][1], addr);
            }

            #pragma unroll
            for (int mi = 0; mi < 2; mi++)
                #pragma unroll
                for (int ni = 0; ni < 8; ni++)
                    MMA_BF16(acc[mi][ni], a[mi], b[ni]);
        }
    }

    // ---- Epilogue: bias + relu, float2 stores ----
    const int qrow = lane >> 2;          // 0..7
    const int qcol = (lane & 3) * 2;     // 0,2,4,6

    float bv[8][2];
    #pragma unroll
    for (int ni = 0; ni < 8; ni++) {
        bv[ni][0] = bias[p * OO + ni * 8 + qcol + 0];
        bv[ni][1] = bias[p * OO + ni * 8 + qcol + 1];
    }

    #pragma unroll
    for (int mi = 0; mi < 2; mi++) {
        const int row = b0 + w32 + mi * 16 + qrow;
        float* o0 = out + (size_t)row * (PP * OO) + p * OO;
        float* o1 = o0 + 8 * (PP * OO);
        #pragma unroll
        for (int ni = 0; ni < 8; ni++) {
            float2 v0, v1;
            v0.x = fmaxf(acc[mi][ni][0] + bv[ni][0], 0.0f);
            v0.y = fmaxf(acc[mi][ni][1] + bv[ni][1], 0.0f);
            v1.x = fmaxf(acc[mi][ni][2] + bv[ni][0], 0.0f);
            v1.y = fmaxf(acc[mi][ni][3] + bv[ni][1], 0.0f);
            *(float2*)(o0 + ni * 8 + qcol) = v0;
            *(float2*)(o1 + ni * 8 + qcol) = v1;
        }
    }
}

extern "C" void kernel_launch(void* const* d_in, const int* in_sizes, int n_in,
                              void* d_out, int out_size)
{
    const float* x    = (const float*)d_in[0];
    const float* W    = (const float*)d_in[1];
    const float* bias = (const float*)d_in[2];
    float* out = (float*)d_out;

    const int B = in_sizes[0] / (PP * KK);   // 16384

    cudaFuncSetAttribute(parts_hmma_kernel,
                         cudaFuncAttributeMaxDynamicSharedMemorySize, SM_TOTAL);

    dim3 grid(B / BLOCK_B, PP);
    parts_hmma_kernel<<<grid, THREADS, SM_TOTAL>>>(x, W, bias, out);
}

// round 4
// speedup vs baseline: 1.9091x; 1.3084x over previous
#include <cuda_runtime.h>
#include <cuda_bf16.h>
#include <cstdint>

// out[b,p,o] = relu(sum_k x[b,p,k] * W[p,k,o] + bias[p,o])
// B=16384, P=K=O=64 fp32.
// CTA = 128 b-rows x one part p, 4 warps, warp tile M=32,N=64.
// A (x) loaded DIRECTLY from global in m16n8k16 fragment layout (float2 per
// lane), split to bf16 hi/lo in registers, software-pipelined over k-chunks.
// W in smem (hi/lo bf16, stride-72 rows) read via ldmatrix.trans.
// 3 split terms: xh*wh + xh*wl + xl*wh, fp32 accumulation.

#define PP 64
#define KK 64
#define OO 64
#define BLOCK_B 128
#define THREADS 128

#define ASTRIDE 72                         // bf16 elems per smem row (144 B)
#define SW_BYTES (KK * ASTRIDE * 2)        // 9216
#define SM_WHI 0
#define SM_WLO (SM_WHI + SW_BYTES)
#define SM_TOTAL (SM_WLO + SW_BYTES)       // 18432

__device__ __forceinline__ uint32_t smem_u32(const void* p) {
    uint32_t a;
    asm("{ .reg .u64 t; cvta.to.shared.u64 t, %1; cvt.u32.u64 %0, t; }" : "=r"(a) : "l"(p));
    return a;
}

// pack word: lo16 = bf16(a), hi16 = bf16(b)
__device__ __forceinline__ uint32_t pack_bf16(float a, float b) {
    uint32_t r;
    asm("cvt.rn.bf16x2.f32 %0, %1, %2;" : "=r"(r) : "f"(b), "f"(a));
    return r;
}
__device__ __forceinline__ float bf_lo(uint32_t h) { return __uint_as_float(h << 16); }
__device__ __forceinline__ float bf_hi(uint32_t h) { return __uint_as_float(h & 0xFFFF0000u); }

#define LDSM_X4_T(r0, r1, r2, r3, addr) \
    asm volatile("ldmatrix.sync.aligned.m8n8.x4.trans.shared.b16 {%0,%1,%2,%3}, [%4];" \
                 : "=r"(r0), "=r"(r1), "=r"(r2), "=r"(r3) : "r"(addr))

#define MMA_BF16(d, a, b0_, b1_) \
    asm volatile("mma.sync.aligned.m16n8k16.row.col.f32.bf16.bf16.f32 " \
                 "{%0,%1,%2,%3}, {%4,%5,%6,%7}, {%8,%9}, {%0,%1,%2,%3};" \
                 : "+f"((d)[0]), "+f"((d)[1]), "+f"((d)[2]), "+f"((d)[3]) \
                 : "r"((a)[0]), "r"((a)[1]), "r"((a)[2]), "r"((a)[3]), \
                   "r"(b0_), "r"(b1_))

extern "C" __global__ void __launch_bounds__(THREADS, 4)
parts_hmma_fused_kernel(const float* __restrict__ x,
                        const float* __restrict__ W,
                        const float* __restrict__ bias,
                        float* __restrict__ out)
{
    extern __shared__ char smem[];
    const uint32_t sb = smem_u32(smem);
    const int t    = threadIdx.x;
    const int wid  = t >> 5;
    const int lane = t & 31;
    const int p    = blockIdx.y;
    const int b0   = blockIdx.x * BLOCK_B;

    const int w32  = wid * 32;
    const int qrow = lane >> 2;          // 0..7
    const int qk   = (lane & 3) * 2;     // 0,2,4,6

    // Per-thread A base: row = b0 + w32 + qrow, col base = qk
    const float* xw = x + (size_t)(b0 + w32 + qrow) * (PP * KK) + p * KK + qk;
    const size_t RS = (size_t)(PP * KK); // row stride in floats

    // ---- Prefetch A chunk ks=0 (8 float2: 2 m-frags x 4 positions) ----
    // frag j mapping: j0:(r+0,k+0) j1:(r+8,k+0) j2:(r+0,k+8) j3:(r+8,k+8)
    float2 xf[8];
    #pragma unroll
    for (int mi = 0; mi < 2; mi++)
        #pragma unroll
        for (int j = 0; j < 4; j++)
            xf[mi * 4 + j] = *(const float2*)(xw + (mi * 16 + (j & 1) * 8) * RS
                                                 + (j >> 1) * 8);

    // ---- W[p]: 64x64 fp32 -> bf16 hi/lo smem, row-major [k][o], stride 72 ----
    #pragma unroll
    for (int i = 0; i < 8; i++) {
        int idx4 = i * 128 + t;
        int k    = idx4 >> 4;
        int c4   = idx4 & 15;
        float4 v = *(const float4*)(W + p * (KK * OO) + k * OO + c4 * 4);
        uint32_t h0 = pack_bf16(v.x, v.y);
        uint32_t h1 = pack_bf16(v.z, v.w);
        uint32_t l0 = pack_bf16(v.x - bf_lo(h0), v.y - bf_hi(h0));
        uint32_t l1 = pack_bf16(v.z - bf_lo(h1), v.w - bf_hi(h1));
        uint32_t off = (uint32_t)(k * (ASTRIDE * 2) + c4 * 8);
        *(uint2*)(smem + SM_WHI + off) = make_uint2(h0, h1);
        *(uint2*)(smem + SM_WLO + off) = make_uint2(l0, l1);
    }
    __syncthreads();

    // ---- Mainloop ----
    const int lrow  = lane & 15;
    const int lcol8 = (lane >> 4) * 8;

    float acc[2][8][4];
    #pragma unroll
    for (int mi = 0; mi < 2; mi++)
        #pragma unroll
        for (int ni = 0; ni < 8; ni++)
            #pragma unroll
            for (int r = 0; r < 4; r++)
                acc[mi][ni][r] = 0.0f;

    #pragma unroll
    for (int ks = 0; ks < 4; ks++) {
        const int k0 = ks * 16;

        // convert current A chunk to hi/lo fragments
        uint32_t ah[2][4], al[2][4];
        #pragma unroll
        for (int mi = 0; mi < 2; mi++)
            #pragma unroll
            for (int j = 0; j < 4; j++) {
                float2 v = xf[mi * 4 + j];
                uint32_t h = pack_bf16(v.x, v.y);
                ah[mi][j] = h;
                al[mi][j] = pack_bf16(v.x - bf_lo(h), v.y - bf_hi(h));
            }

        // prefetch next chunk
        if (ks < 3) {
            #pragma unroll
            for (int mi = 0; mi < 2; mi++)
                #pragma unroll
                for (int j = 0; j < 4; j++)
                    xf[mi * 4 + j] = *(const float2*)(xw + (mi * 16 + (j & 1) * 8) * RS
                                                         + (ks + 1) * 16 + (j >> 1) * 8);
        }

        #pragma unroll
        for (int ng = 0; ng < 4; ng++) {
            uint32_t bh[4], bl[4];
            uint32_t ahi = sb + SM_WHI
                + (uint32_t)((k0 + lrow) * (ASTRIDE * 2) + (ng * 16 + lcol8) * 2);
            uint32_t alo = sb + SM_WLO
                + (uint32_t)((k0 + lrow) * (ASTRIDE * 2) + (ng * 16 + lcol8) * 2);
            LDSM_X4_T(bh[0], bh[1], bh[2], bh[3], ahi);
            LDSM_X4_T(bl[0], bl[1], bl[2], bl[3], alo);

            #pragma unroll
            for (int mi = 0; mi < 2; mi++) {
                MMA_BF16(acc[mi][2 * ng + 0], ah[mi], bh[0], bh[1]);
                MMA_BF16(acc[mi][2 * ng + 1], ah[mi], bh[2], bh[3]);
                MMA_BF16(acc[mi][2 * ng + 0], ah[mi], bl[0], bl[1]);
                MMA_BF16(acc[mi][2 * ng + 1], ah[mi], bl[2], bl[3]);
                MMA_BF16(acc[mi][2 * ng + 0], al[mi], bh[0], bh[1]);
                MMA_BF16(acc[mi][2 * ng + 1], al[mi], bh[2], bh[3]);
            }
        }
    }

    // ---- Epilogue: bias + relu, float2 stores ----
    const int qcol = qk;                 // same (lane&3)*2

    #pragma unroll
    for (int mi = 0; mi < 2; mi++) {
        const int row = b0 + w32 + mi * 16 + qrow;
        float* o0 = out + (size_t)row * RS + p * OO;
        float* o1 = o0 + 8 * RS;
        #pragma unroll
        for (int ni = 0; ni < 8; ni++) {
            float2 bv = *(const float2*)(bias + p * OO + ni * 8 + qcol);
            float2 v0, v1;
            v0.x = fmaxf(acc[mi][ni][0] + bv.x, 0.0f);
            v0.y = fmaxf(acc[mi][ni][1] + bv.y, 0.0f);
            v1.x = fmaxf(acc[mi][ni][2] + bv.x, 0.0f);
            v1.y = fmaxf(acc[mi][ni][3] + bv.y, 0.0f);
            *(float2*)(o0 + ni * 8 + qcol) = v0;
            *(float2*)(o1 + ni * 8 + qcol) = v1;
        }
    }
}

extern "C" void kernel_launch(void* const* d_in, const int* in_sizes, int n_in,
                              void* d_out, int out_size)
{
    const float* x    = (const float*)d_in[0];
    const float* W    = (const float*)d_in[1];
    const float* bias = (const float*)d_in[2];
    float* out = (float*)d_out;

    const int B = in_sizes[0] / (PP * KK);   // 16384

    cudaFuncSetAttribute(parts_hmma_fused_kernel,
                         cudaFuncAttributeMaxDynamicSharedMemorySize, SM_TOTAL);

    dim3 grid(B / BLOCK_B, PP);
    parts_hmma_fused_kernel<<<grid, THREADS, SM_TOTAL>>>(x, W, bias, out);
}

// round 5
// speedup vs baseline: 2.2568x; 1.1821x over previous
#include <cuda_runtime.h>
#include <cuda_bf16.h>
#include <cstdint>

// out[b,p,o] = relu(sum_k x[b,p,k] * W[p,k,o] + bias[p,o])
// B=16384, P=K=O=64 fp32.
// CTA = 128 b-rows x one part p, 4 warps, warp tile M=32,N=64.
// Split-bf16 (hi+lo), 3 MMA terms, fp32 accum, mma.sync.m16n8k16.
// sigma: k-permutation (A loads become LDG.128 in fragment layout)
// tau:   n-permutation (C stores become STG.128, 4 contiguous cols/thread)
// Both realized by permuting the one-time W smem store.

#define PP 64
#define KK 64
#define OO 64
#define BLOCK_B 128
#define THREADS 128

#define ASTRIDE 72                         // bf16 elems per smem row (144 B)
#define ROWB (ASTRIDE * 2)                 // 144 bytes per smem row
#define SW_BYTES (KK * ROWB)               // 9216
#define SM_WHI 0
#define SM_WLO (SM_WHI + SW_BYTES)
#define SM_TOTAL (SM_WLO + SW_BYTES)       // 18432

__device__ __forceinline__ uint32_t smem_u32(const void* p) {
    uint32_t a;
    asm("{ .reg .u64 t; cvta.to.shared.u64 t, %1; cvt.u32.u64 %0, t; }" : "=r"(a) : "l"(p));
    return a;
}

// pack word: lo16 = bf16(a), hi16 = bf16(b)
__device__ __forceinline__ uint32_t pack_bf16(float a, float b) {
    uint32_t r;
    asm("cvt.rn.bf16x2.f32 %0, %1, %2;" : "=r"(r) : "f"(b), "f"(a));
    return r;
}
__device__ __forceinline__ float bf_lo(uint32_t h) { return __uint_as_float(h << 16); }
__device__ __forceinline__ float bf_hi(uint32_t h) { return __uint_as_float(h & 0xFFFF0000u); }

#define LDSM_X4_T(r0, r1, r2, r3, addr) \
    asm volatile("ldmatrix.sync.aligned.m8n8.x4.trans.shared.b16 {%0,%1,%2,%3}, [%4];" \
                 : "=r"(r0), "=r"(r1), "=r"(r2), "=r"(r3) : "r"(addr))

#define MMA_BF16(d, a, b0_, b1_) \
    asm volatile("mma.sync.aligned.m16n8k16.row.col.f32.bf16.bf16.f32 " \
                 "{%0,%1,%2,%3}, {%4,%5,%6,%7}, {%8,%9}, {%0,%1,%2,%3};" \
                 : "+f"((d)[0]), "+f"((d)[1]), "+f"((d)[2]), "+f"((d)[3]) \
                 : "r"((a)[0]), "r"((a)[1]), "r"((a)[2]), "r"((a)[3]), \
                   "r"(b0_), "r"(b1_))

extern "C" __global__ void __launch_bounds__(THREADS, 4)
parts_hmma_perm_kernel(const float* __restrict__ x,
                       const float* __restrict__ W,
                       const float* __restrict__ bias,
                       float* __restrict__ out)
{
    extern __shared__ char smem[];
    const uint32_t sb = smem_u32(smem);
    const int t    = threadIdx.x;
    const int wid  = t >> 5;
    const int lane = t & 31;
    const int p    = blockIdx.y;
    const int b0   = blockIdx.x * BLOCK_B;

    const int w32  = wid * 32;
    const int qrow = lane >> 2;          // 0..7
    const int q4   = (lane & 3) * 4;     // phys-k / out-col quad offset

    const size_t RS = (size_t)(PP * KK); // 4096 floats, batch row stride

    // Per-thread A base: phys cols q4..q4+3 of each 16-k chunk.
    const float* xq = x + (size_t)(b0 + w32 + qrow) * RS + p * KK + q4;

    // ---- Prefetch A chunk ks=0: [mi][rowsel] ----
    float4 xf[2][2];
    #pragma unroll
    for (int mi = 0; mi < 2; mi++)
        #pragma unroll
        for (int rs = 0; rs < 2; rs++)
            xf[mi][rs] = *(const float4*)(xq + (mi * 16 + rs * 8) * RS);

    // ---- W[p] -> smem with sigma (rows) and tau (cols) permutations ----
    // sigma: phys k -> smem row sr = (k&~15) + 2*((k>>2)&3) + (k&1) + 8*((k>>1)&1)
    // tau:   phys o (=c4*4+j) -> smem col (2*(c4>>2)+(j>>1))*8 + 2*(c4&3) + (j&1)
    #pragma unroll
    for (int i = 0; i < 8; i++) {
        int idx4 = i * 128 + t;
        int k    = idx4 >> 4;
        int c4   = idx4 & 15;
        float4 v = *(const float4*)(W + p * (KK * OO) + k * OO + c4 * 4);
        uint32_t h0 = pack_bf16(v.x, v.y);
        uint32_t h1 = pack_bf16(v.z, v.w);
        uint32_t l0 = pack_bf16(v.x - bf_lo(h0), v.y - bf_hi(h0));
        uint32_t l1 = pack_bf16(v.z - bf_lo(h1), v.w - bf_hi(h1));
        int w  = k & 15;
        int sr = (k & ~15) + 2 * (w >> 2) + (w & 1) + 8 * ((w >> 1) & 1);
        int col0 = (2 * (c4 >> 2)) * 8 + 2 * (c4 & 3);   // bf16 units, pair j=0,1
        int col1 = col0 + 8;                              // pair j=2,3
        uint32_t base = (uint32_t)(sr * ROWB);
        *(uint32_t*)(smem + SM_WHI + base + col0 * 2) = h0;
        *(uint32_t*)(smem + SM_WHI + base + col1 * 2) = h1;
        *(uint32_t*)(smem + SM_WLO + base + col0 * 2) = l0;
        *(uint32_t*)(smem + SM_WLO + base + col1 * 2) = l1;
    }
    __syncthreads();

    // ---- Mainloop ----
    const int lrow  = lane & 15;
    const int lcol8 = (lane >> 4) * 8;

    float acc[2][8][4];
    #pragma unroll
    for (int mi = 0; mi < 2; mi++)
        #pragma unroll
        for (int ni = 0; ni < 8; ni++)
            #pragma unroll
            for (int r = 0; r < 4; r++)
                acc[mi][ni][r] = 0.0f;

    #pragma unroll
    for (int ks = 0; ks < 4; ks++) {
        const int k0 = ks * 16;

        // Convert current A chunk to hi/lo fragments.
        // a0 <- (rs0).xy, a1 <- (rs1).xy, a2 <- (rs0).zw, a3 <- (rs1).zw
        uint32_t ah[2][4], al[2][4];
        #pragma unroll
        for (int mi = 0; mi < 2; mi++) {
            float4 v0 = xf[mi][0];
            float4 v1 = xf[mi][1];
            uint32_t h;
            h = pack_bf16(v0.x, v0.y); ah[mi][0] = h;
            al[mi][0] = pack_bf16(v0.x - bf_lo(h), v0.y - bf_hi(h));
            h = pack_bf16(v1.x, v1.y); ah[mi][1] = h;
            al[mi][1] = pack_bf16(v1.x - bf_lo(h), v1.y - bf_hi(h));
            h = pack_bf16(v0.z, v0.w); ah[mi][2] = h;
            al[mi][2] = pack_bf16(v0.z - bf_lo(h), v0.w - bf_hi(h));
            h = pack_bf16(v1.z, v1.w); ah[mi][3] = h;
            al[mi][3] = pack_bf16(v1.z - bf_lo(h), v1.w - bf_hi(h));
        }

        // Prefetch next chunk
        if (ks < 3) {
            #pragma unroll
            for (int mi = 0; mi < 2; mi++)
                #pragma unroll
                for (int rs = 0; rs < 2; rs++)
                    xf[mi][rs] = *(const float4*)(xq + (mi * 16 + rs * 8) * RS
                                                     + (ks + 1) * 16);
        }

        #pragma unroll
        for (int ng = 0; ng < 4; ng++) {
            uint32_t bh[4], bl[4];
            uint32_t off = (uint32_t)((k0 + lrow) * ROWB + (ng * 16 + lcol8) * 2);
            LDSM_X4_T(bh[0], bh[1], bh[2], bh[3], sb + SM_WHI + off);
            LDSM_X4_T(bl[0], bl[1], bl[2], bl[3], sb + SM_WLO + off);

            #pragma unroll
            for (int mi = 0; mi < 2; mi++) {
                MMA_BF16(acc[mi][2 * ng + 0], ah[mi], bh[0], bh[1]);
                MMA_BF16(acc[mi][2 * ng + 1], ah[mi], bh[2], bh[3]);
                MMA_BF16(acc[mi][2 * ng + 0], ah[mi], bl[0], bl[1]);
                MMA_BF16(acc[mi][2 * ng + 1], ah[mi], bl[2], bl[3]);
                MMA_BF16(acc[mi][2 * ng + 0], al[mi], bh[0], bh[1]);
                MMA_BF16(acc[mi][2 * ng + 1], al[mi], bh[2], bh[3]);
            }
        }
    }

    // ---- Epilogue (tau): thread owns out cols g*16 + q4 .. +3 ----
    float4 bv[4];
    #pragma unroll
    for (int g = 0; g < 4; g++)
        bv[g] = *(const float4*)(bias + p * OO + g * 16 + q4);

    #pragma unroll
    for (int mi = 0; mi < 2; mi++) {
        #pragma unroll
        for (int rs = 0; rs < 2; rs++) {
            const int row = b0 + w32 + mi * 16 + rs * 8 + qrow;
            float* op = out + (size_t)row * RS + p * OO + q4;
            #pragma unroll
            for (int g = 0; g < 4; g++) {
                float4 v;
                v.x = fmaxf(acc[mi][2 * g + 0][rs * 2 + 0] + bv[g].x, 0.0f);
                v.y = fmaxf(acc[mi][2 * g + 0][rs * 2 + 1] + bv[g].y, 0.0f);
                v.z = fmaxf(acc[mi][2 * g + 1][rs * 2 + 0] + bv[g].z, 0.0f);
                v.w = fmaxf(acc[mi][2 * g + 1][rs * 2 + 1] + bv[g].w, 0.0f);
                *(float4*)(op + g * 16) = v;
            }
        }
    }
}

extern "C" void kernel_launch(void* const* d_in, const int* in_sizes, int n_in,
                              void* d_out, int out_size)
{
    const float* x    = (const float*)d_in[0];
    const float* W    = (const float*)d_in[1];
    const float* bias = (const float*)d_in[2];
    float* out = (float*)d_out;

    const int B = in_sizes[0] / (PP * KK);   // 16384

    cudaFuncSetAttribute(parts_hmma_perm_kernel,
                         cudaFuncAttributeMaxDynamicSharedMemorySize, SM_TOTAL);

    dim3 grid(B / BLOCK_B, PP);
    parts_hmma_perm_kernel<<<grid, THREADS, SM_TOTAL>>>(x, W, bias, out);
}